// round 12
// baseline (speedup 1.0000x reference)
#include <cuda_runtime.h>
#include <cstdint>

#define Bdim 64
#define Sdim 512
#define Wdim 256
#define Ddim 768
#define Ndim 96            // 32 attrs * 3 classes
#define KC   32            // K chunk
#define MT   64            // M tile per CTA
#define NITER (Ddim / KC)  // 24
#define SA_STRIDE 36       // padded row stride (floats): bank = lane for frag loads

__device__ __forceinline__ uint32_t f2tf32(float f) {
    uint32_t r;
    asm("cvt.rna.tf32.f32 %0, %1;" : "=r"(r) : "f"(f));
    return r;
}

__device__ __forceinline__ void mma_tf32(float* c,
    uint32_t a0, uint32_t a1, uint32_t a2, uint32_t a3,
    uint32_t b0, uint32_t b1)
{
    asm volatile(
        "mma.sync.aligned.m16n8k8.row.col.f32.tf32.tf32.f32 "
        "{%0,%1,%2,%3}, {%4,%5,%6,%7}, {%8,%9}, {%0,%1,%2,%3};"
        : "+f"(c[0]), "+f"(c[1]), "+f"(c[2]), "+f"(c[3])
        : "r"(a0), "r"(a1), "r"(a2), "r"(a3), "r"(b0), "r"(b1));
}

__global__ __launch_bounds__(256, 2)
void ner_gather_gemm(const float* __restrict__ seq,
                     const int*   __restrict__ widx,
                     const float* __restrict__ wgt,
                     const float* __restrict__ bias,
                     float*       __restrict__ out)
{
    __shared__ float sA[2][MT * SA_STRIDE];     // 2 x 9 KB
    __shared__ float sB[2][Ndim * SA_STRIDE];   // 2 x 13.5 KB
    __shared__ int   sIdx[MT];
    __shared__ float sBias[Ndim];

    const int t      = threadIdx.x;
    const int m_base = blockIdx.x * MT;        // 64 consecutive (b,w) rows, same b
    const int bidx   = m_base >> 8;            // b (W=256, MT=64 divides)

    if (t < MT)   sIdx[t]  = widx[m_base + t];
    if (t < Ndim) sBias[t] = bias[t];
    __syncthreads();

    // A staging: thread t loads row rA, 8-col slice part (4 threads per 32-col row)
    const int rA   = t >> 2;                   // 0..63
    const int part = t & 3;                    // 0..3
    const float* aRow = seq + (size_t)(bidx * Sdim + sIdx[rA]) * Ddim + part * 8;
    const int aOff = rA * SA_STRIDE + part * 8;

    // B staging: 96*32 floats / 256 thr = 12 floats = 3 float4 per thread
    int  bOff[3];
    const float* wPtr[3];
    #pragma unroll
    for (int j = 0; j < 3; j++) {
        int i = t + 256 * j;
        int n = i >> 3, c = (i & 7) * 4;
        bOff[j] = n * SA_STRIDE + c;
        wPtr[j] = wgt + n * Ddim + c;
    }

    float4 ra[2];
    float4 rb[3];

    const int wid  = t >> 5;
    const int lane = t & 31;
    const int grp  = lane >> 2;   // 0..7
    const int kq   = lane & 3;    // 0..3
    const int wm   = wid & 3;     // M group (16 rows each)
    const int wn   = wid >> 2;    // N half (48 cols each)
    const int rowA  = wm * 16 + grp;
    const int nbase = wn * 48;

    float acc[6][4];
    #pragma unroll
    for (int i = 0; i < 6; i++) {
        acc[i][0] = 0.f; acc[i][1] = 0.f; acc[i][2] = 0.f; acc[i][3] = 0.f;
    }

    // ---- prefetch + stage chunk 0 into buffer 0 ----
    ra[0] = *reinterpret_cast<const float4*>(aRow + 0);
    ra[1] = *reinterpret_cast<const float4*>(aRow + 4);
    #pragma unroll
    for (int j = 0; j < 3; j++)
        rb[j] = *reinterpret_cast<const float4*>(wPtr[j]);

    {
        uint4 u0 = { f2tf32(ra[0].x), f2tf32(ra[0].y), f2tf32(ra[0].z), f2tf32(ra[0].w) };
        uint4 u1 = { f2tf32(ra[1].x), f2tf32(ra[1].y), f2tf32(ra[1].z), f2tf32(ra[1].w) };
        *reinterpret_cast<uint4*>(&sA[0][aOff    ]) = u0;
        *reinterpret_cast<uint4*>(&sA[0][aOff + 4]) = u1;
        #pragma unroll
        for (int j = 0; j < 3; j++) {
            uint4 u = { f2tf32(rb[j].x), f2tf32(rb[j].y), f2tf32(rb[j].z), f2tf32(rb[j].w) };
            *reinterpret_cast<uint4*>(&sB[0][bOff[j]]) = u;
        }
    }
    __syncthreads();

    #pragma unroll 1
    for (int it = 0; it < NITER; ++it) {
        const int cur = it & 1;

        // prefetch next chunk into registers (hidden under compute)
        if (it + 1 < NITER) {
            const int kc = (it + 1) * KC;
            ra[0] = *reinterpret_cast<const float4*>(aRow + kc);
            ra[1] = *reinterpret_cast<const float4*>(aRow + kc + 4);
            #pragma unroll
            for (int j = 0; j < 3; j++)
                rb[j] = *reinterpret_cast<const float4*>(wPtr[j] + kc);
        }

        // compute current chunk from smem stage `cur`
        #pragma unroll
        for (int k8 = 0; k8 < KC; k8 += 8) {
            uint32_t a0 = __float_as_uint(sA[cur][ rowA      * SA_STRIDE + k8 + kq    ]);
            uint32_t a1 = __float_as_uint(sA[cur][(rowA + 8) * SA_STRIDE + k8 + kq    ]);
            uint32_t a2 = __float_as_uint(sA[cur][ rowA      * SA_STRIDE + k8 + kq + 4]);
            uint32_t a3 = __float_as_uint(sA[cur][(rowA + 8) * SA_STRIDE + k8 + kq + 4]);
            #pragma unroll
            for (int nt = 0; nt < 6; ++nt) {
                int n = nbase + nt * 8 + grp;
                uint32_t b0 = __float_as_uint(sB[cur][n * SA_STRIDE + k8 + kq    ]);
                uint32_t b1 = __float_as_uint(sB[cur][n * SA_STRIDE + k8 + kq + 4]);
                mma_tf32(acc[nt], a0, a1, a2, a3, b0, b1);
            }
        }

        // stage next chunk into the other buffer; single barrier per iter
        if (it + 1 < NITER) {
            const int nxt = cur ^ 1;
            uint4 u0 = { f2tf32(ra[0].x), f2tf32(ra[0].y), f2tf32(ra[0].z), f2tf32(ra[0].w) };
            uint4 u1 = { f2tf32(ra[1].x), f2tf32(ra[1].y), f2tf32(ra[1].z), f2tf32(ra[1].w) };
            *reinterpret_cast<uint4*>(&sA[nxt][aOff    ]) = u0;
            *reinterpret_cast<uint4*>(&sA[nxt][aOff + 4]) = u1;
            #pragma unroll
            for (int j = 0; j < 3; j++) {
                uint4 u = { f2tf32(rb[j].x), f2tf32(rb[j].y), f2tf32(rb[j].z), f2tf32(rb[j].w) };
                *reinterpret_cast<uint4*>(&sB[nxt][bOff[j]]) = u;
            }
            __syncthreads();
        }
    }

    // ---- epilogue: bias add + scattered store into [A, B, W, 3] layout ----
    #pragma unroll
    for (int nt = 0; nt < 6; ++nt) {
        #pragma unroll
        for (int e = 0; e < 4; ++e) {
            int n = nbase + nt * 8 + 2 * kq + (e & 1);   // column in [0,96)
            int m = m_base + rowA + (e >> 1) * 8;        // global row (b*W + w)
            float v = acc[nt][e] + sBias[n];
            int a = n / 3;
            int c = n - a * 3;
            out[(size_t)a * (Bdim * Wdim * 3) + (size_t)m * 3 + c] = v;
        }
    }
}

extern "C" void kernel_launch(void* const* d_in, const int* in_sizes, int n_in,
                              void* d_out, int out_size)
{
    const float* seq  = (const float*)d_in[0];   // [64, 512, 768] f32
    const int*   widx = (const int*)  d_in[1];   // [64, 256] i32
    const float* wgt  = (const float*)d_in[2];   // [32, 3, 768] f32
    const float* bias = (const float*)d_in[3];   // [32, 3] f32
    float* out = (float*)d_out;                  // [32, 64, 256, 3] f32

    ner_gather_gemm<<<(Bdim * Wdim) / MT, 256>>>(seq, widx, wgt, bias, out);
}